// round 4
// baseline (speedup 1.0000x reference)
#include <cuda_runtime.h>

#define BATCH   8
#define NDATA   8192
#define NPOINT  1024
#define NSAMPLE 32
#define CFEAT   64
#define RADIUSF 0.2f
#define T_LOOSE 0.0404f

#define NP_SIZE  (BATCH*NPOINT*NSAMPLE*(3+CFEAT))   /* 17563648 */
#define IDX_OFF  NP_SIZE
#define IDX_SIZE (BATCH*NPOINT*NSAMPLE)             /* 262144 */
#define GX_OFF   (IDX_OFF + IDX_SIZE)

#define QB  16    /* queries per block             */
#define WPB 4     /* warps per block (scan chunks) */
#define THR (WPB*32)
#define CHUNK (NDATA/WPB)                            /* 2048 */
#define CAP 64    /* candidate capacity per query  */

__global__ __launch_bounds__(THR)
void k_search(const float* __restrict__ new_xyz,
              const float* __restrict__ xyz,
              float* __restrict__ out)
{
    __shared__ float s_cd[QB][CAP];
    __shared__ int   s_ci[QB][CAP];
    __shared__ int   s_cnt[QB];
    __shared__ int   s_out[QB][NSAMPLE];
    __shared__ float s_qx[QB], s_qy[QB], s_qz[QB];
    __shared__ unsigned long long s_best[QB];

    const int b    = blockIdx.y;
    const int w    = threadIdx.x >> 5;
    const int lane = threadIdx.x & 31;
    const int p0   = blockIdx.x * QB;

    if (threadIdx.x < QB) {
        s_cnt[threadIdx.x]  = 0;
        s_best[threadIdx.x] = ~0ull;
        const float* qp = new_xyz + ((size_t)b*NPOINT + p0 + threadIdx.x) * 3;
        s_qx[threadIdx.x] = qp[0];
        s_qy[threadIdx.x] = qp[1];
        s_qz[threadIdx.x] = qp[2];
    }
    __syncthreads();

    // per-thread query constants (compile-time indexed -> registers)
    float nqx[QB], nqy[QB], nqz[QB], qt[QB];
#pragma unroll
    for (int q = 0; q < QB; q++) {
        float cx = s_qx[q], cy = s_qy[q], cz = s_qz[q];
        nqx[q] = -2.0f*cx; nqy[q] = -2.0f*cy; nqz[q] = -2.0f*cz;
        // loose test: |p|^2 - 2 p.q < T_LOOSE - |q|^2
        qt[q] = T_LOOSE - fmaf(cx,cx, fmaf(cy,cy, cz*cz));
    }

    const float* X = xyz + (size_t)b*NDATA*3;

    // ---- hot loop: 2 points/iter, branchless masks, rare slow path --------
    const int base = w*CHUNK;
    for (int off = lane; off < CHUNK; off += 64) {
        const int pa = base + off;
        const int pb = pa + 32;

        float ax = X[3*pa+0], ay = X[3*pa+1], az = X[3*pa+2];
        float bx = X[3*pb+0], by = X[3*pb+1], bz = X[3*pb+2];
        float apw = fmaf(ax,ax, fmaf(ay,ay, az*az));
        float bpw = fmaf(bx,bx, fmaf(by,by, bz*bz));

        unsigned ma = 0, mb = 0;
#pragma unroll
        for (int q = 0; q < QB; q++) {
            float la = fmaf(ax, nqx[q], fmaf(ay, nqy[q], fmaf(az, nqz[q], apw)));
            float lb = fmaf(bx, nqx[q], fmaf(by, nqy[q], fmaf(bz, nqz[q], bpw)));
            if (la < qt[q]) ma |= (1u << q);
            if (lb < qt[q]) mb |= (1u << q);
        }
        unsigned mm = ma | (mb << 16);
        while (mm) {
            int pos = __ffs(mm) - 1;
            mm &= mm - 1;
            int q  = pos & 15;
            int pt = (pos < 16) ? pa : pb;
            float px = (pos < 16) ? ax : bx;
            float py = (pos < 16) ? ay : by;
            float pz = (pos < 16) ? az : bz;
            // exact recompute matching reference arithmetic
            float dx = px - s_qx[q];
            float dy = py - s_qy[q];
            float dz = pz - s_qz[q];
            float e = __fadd_rn(__fadd_rn(__fmul_rn(dx,dx), __fmul_rn(dy,dy)),
                                __fmul_rn(dz,dz));
            float d = __fsqrt_rn(e);
            if (d < RADIUSF) {
                int slot = atomicAdd(&s_cnt[q], 1);
                if (slot < CAP) { s_cd[q][slot] = d; s_ci[q][slot] = pt; }
            }
        }
    }
    __syncthreads();

    // ---- block-cooperative argmin for rare empty queries ------------------
    for (int q = 0; q < QB; q++) {
        if (s_cnt[q] != 0) continue;
        float cx = s_qx[q], cy = s_qy[q], cz = s_qz[q];
        float bd = 3.4e38f; int bi = 0;
        for (int pt = threadIdx.x; pt < NDATA; pt += THR) {
            float dx = X[3*pt+0] - cx;
            float dy = X[3*pt+1] - cy;
            float dz = X[3*pt+2] - cz;
            float e  = __fadd_rn(__fadd_rn(__fmul_rn(dx,dx), __fmul_rn(dy,dy)),
                                 __fmul_rn(dz,dz));
            float d  = __fsqrt_rn(e);
            if (d < bd) { bd = d; bi = pt; }   // strict < keeps lowest idx on tie
        }
        unsigned long long pack =
            ((unsigned long long)__float_as_uint(bd) << 32) | (unsigned)bi;
        atomicMin(&s_best[q], pack);
    }
    __syncthreads();

    // ---- rank candidates: warp w handles queries 4w..4w+3 -----------------
    for (int qq = 0; qq < QB/WPB; qq++) {
        const int q = w*(QB/WPB) + qq;
        const int n = min(s_cnt[q], CAP);
        const int p = p0 + q;
        float* orow = out + IDX_OFF + ((size_t)(b*NPOINT + p))*NSAMPLE;

        if (n == 0) {
            int bi = (int)(s_best[q] & 0xffffffffull);
            orow[lane] = (float)bi;
        } else {
            for (int i = lane; i < n; i += 32) {
                float di = s_cd[q][i]; int ii = s_ci[q][i];
                int rank = 0;
                for (int j = 0; j < n; j++) {
                    float dj = s_cd[q][j]; int ij = s_ci[q][j];
                    rank += (dj < di) || (dj == di && ij < ii);
                }
                if (rank < NSAMPLE) s_out[q][rank] = ii;
            }
            __syncwarp();
            int nearest = s_out[q][0];
            int v = (lane < n) ? s_out[q][lane] : nearest;
            orow[lane] = (float)v;
        }
        __syncwarp();
    }
}

__global__ __launch_bounds__(256)
void k_gather(const float* __restrict__ xyz,
              const float* __restrict__ points,
              float* __restrict__ out)
{
    const int g = threadIdx.x >> 6;   // 4 rows per block
    const int c = threadIdx.x & 63;
    const long r = (long)blockIdx.x * 4 + g;   // 0 .. 262143

    const int b  = (int)(r >> 15);

    const int id = (int)out[IDX_OFF + r];

    const float* prow = points + ((size_t)b*NDATA + id)*CFEAT;
    out[r*67 + 3 + c] = prow[c];

    if (c < 3) {
        float xv = xyz[((size_t)b*NDATA + id)*3 + c];
        out[r*67 + c]         = xv;
        out[GX_OFF + r*3 + c] = xv;
    }
}

extern "C" void kernel_launch(void* const* d_in, const int* in_sizes, int n_in,
                              void* d_out, int out_size)
{
    const float *new_xyz = nullptr, *xyz = nullptr, *points = nullptr;
    for (int i = 0; i < n_in; i++) {
        if      (in_sizes[i] == BATCH*NPOINT*3)     new_xyz = (const float*)d_in[i];
        else if (in_sizes[i] == BATCH*NDATA*3)      xyz     = (const float*)d_in[i];
        else if (in_sizes[i] == BATCH*NDATA*CFEAT)  points  = (const float*)d_in[i];
    }
    float* out = (float*)d_out;

    dim3 gs(NPOINT/QB, BATCH);
    k_search<<<gs, THR>>>(new_xyz, xyz, out);

    k_gather<<<(BATCH*NPOINT*NSAMPLE)/4, 256>>>(xyz, points, out);
}

// round 6
// speedup vs baseline: 2.1547x; 2.1547x over previous
#include <cuda_runtime.h>

#define BATCH   8
#define NDATA   8192
#define NPOINT  1024
#define NSAMPLE 32
#define CFEAT   64
#define RADIUSF 0.2f
#define T_LOOSE 0.0404f

#define NP_SIZE  (BATCH*NPOINT*NSAMPLE*(3+CFEAT))   /* 17563648 */
#define IDX_OFF  NP_SIZE
#define IDX_SIZE (BATCH*NPOINT*NSAMPLE)             /* 262144 */
#define GX_OFF   (IDX_OFF + IDX_SIZE)

#define QB  16   /* queries per block             */
#define WPB 8    /* warps per block (scan chunks) */
#define CHUNK (NDATA/WPB)                           /* 1024 */
#define CAP 64   /* candidate capacity per query  */

#define GU  8    /* rows per thread in gather     */

__device__ float4 g_pts[BATCH*NDATA];   /* (x, y, z, |p|^2) */

__global__ void k_transpose(const float* __restrict__ xyz)
{
    int t = blockIdx.x * blockDim.x + threadIdx.x;
    if (t < BATCH*NDATA) {
        float x = xyz[3*t + 0];
        float y = xyz[3*t + 1];
        float z = xyz[3*t + 2];
        float pp = fmaf(x, x, fmaf(y, y, z*z));
        g_pts[t] = make_float4(x, y, z, pp);
    }
}

__global__ __launch_bounds__(WPB*32)
void k_search(const float* __restrict__ new_xyz, float* __restrict__ out)
{
    __shared__ float s_cd[QB][CAP];
    __shared__ int   s_ci[QB][CAP];
    __shared__ int   s_cnt[QB];
    __shared__ int   s_out[QB][NSAMPLE];
    __shared__ float s_qx[QB], s_qy[QB], s_qz[QB];

    const int b    = blockIdx.y;
    const int w    = threadIdx.x >> 5;
    const int lane = threadIdx.x & 31;
    const int p0   = blockIdx.x * QB;

    if (threadIdx.x < QB) {
        s_cnt[threadIdx.x] = 0;
        const float* qp = new_xyz + ((size_t)b*NPOINT + p0 + threadIdx.x) * 3;
        s_qx[threadIdx.x] = qp[0];
        s_qy[threadIdx.x] = qp[1];
        s_qz[threadIdx.x] = qp[2];
    }
    __syncthreads();

    // per-thread query constants (compile-time indexed -> registers)
    float nqx[QB], nqy[QB], nqz[QB], qt[QB];
#pragma unroll
    for (int q = 0; q < QB; q++) {
        float cx = s_qx[q], cy = s_qy[q], cz = s_qz[q];
        nqx[q] = -2.0f*cx; nqy[q] = -2.0f*cy; nqz[q] = -2.0f*cz;
        // loose test: |p|^2 - 2 p.q < T_LOOSE - |q|^2
        qt[q] = T_LOOSE - fmaf(cx,cx, fmaf(cy,cy, cz*cz));
    }

    const float4* pts = g_pts + b*NDATA;

    // ---- hot loop: branchless mask, rare slow path ------------------------
    const int ptEnd = (w+1)*CHUNK;
    for (int pt = w*CHUNK + lane; pt < ptEnd; pt += 32) {
        float4 P = pts[pt];
        unsigned m = 0;
#pragma unroll
        for (int q = 0; q < QB; q++) {
            float l = fmaf(P.x, nqx[q], fmaf(P.y, nqy[q], fmaf(P.z, nqz[q], P.w)));
            if (l < qt[q]) m |= (1u << q);
        }
        while (m) {
            int q = __ffs(m) - 1;
            m &= m - 1;
            // exact recompute matching reference arithmetic
            float dx = P.x - s_qx[q];
            float dy = P.y - s_qy[q];
            float dz = P.z - s_qz[q];
            float e = __fadd_rn(__fadd_rn(__fmul_rn(dx,dx), __fmul_rn(dy,dy)),
                                __fmul_rn(dz,dz));
            float d = __fsqrt_rn(e);
            if (d < RADIUSF) {
                int slot = atomicAdd(&s_cnt[q], 1);
                if (slot < CAP) { s_cd[q][slot] = d; s_ci[q][slot] = pt; }
            }
        }
    }
    __syncthreads();

    // ---- rank candidates: warp w handles queries 2w, 2w+1 -----------------
    for (int qq = 0; qq < QB/WPB; qq++) {
        const int q = w*(QB/WPB) + qq;
        const int n = min(s_cnt[q], CAP);
        const int p = p0 + q;

        if (n == 0) {
            // rare: nothing within radius -> global argmin
            float cx = s_qx[q], cy = s_qy[q], cz = s_qz[q];
            float bd = 3.4e38f; int bi = 0;
            for (int pt = lane; pt < NDATA; pt += 32) {
                float4 P = pts[pt];
                float dx = P.x - cx;
                float dy = P.y - cy;
                float dz = P.z - cz;
                float e  = __fadd_rn(__fadd_rn(__fmul_rn(dx,dx), __fmul_rn(dy,dy)),
                                     __fmul_rn(dz,dz));
                if (e < bd) { bd = e; bi = pt; }
            }
#pragma unroll
            for (int off = 16; off >= 1; off >>= 1) {
                float od = __shfl_xor_sync(0xffffffffu, bd, off);
                int   oi = __shfl_xor_sync(0xffffffffu, bi, off);
                if (od < bd || (od == bd && oi < bi)) { bd = od; bi = oi; }
            }
            s_out[q][lane] = bi;
        } else {
            for (int i = lane; i < n; i += 32) {
                float di = s_cd[q][i]; int ii = s_ci[q][i];
                int rank = 0;
                for (int j = 0; j < n; j++) {
                    float dj = s_cd[q][j]; int ij = s_ci[q][j];
                    rank += (dj < di) || (dj == di && ij < ii);
                }
                if (rank < NSAMPLE) s_out[q][rank] = ii;
            }
            __syncwarp();
            int nearest = s_out[q][0];
            if (lane >= n) s_out[q][lane] = nearest;
        }
        __syncwarp();

        out[IDX_OFF + ((size_t)(b*NPOINT + p))*NSAMPLE + lane] = (float)s_out[q][lane];
    }
}

// Each block: 4 thread-groups of 64; each group handles GU rows (stride 4).
// All loads for the GU rows are issued in batches -> MLP ~= GU per stage.
__global__ __launch_bounds__(256)
void k_gather(const float* __restrict__ xyz,
              const float* __restrict__ points,
              float* __restrict__ out)
{
    const int g  = threadIdx.x >> 6;   // 0..3
    const int c  = threadIdx.x & 63;
    const long r0 = (long)blockIdx.x * (4*GU) + g;   // rows r0, r0+4, ...
    const int b   = (int)((blockIdx.x * (4*GU)) >> 15);   // uniform per block

    const float* P = points + (size_t)b*NDATA*CFEAT;
    const float* Xb = xyz   + (size_t)b*NDATA*3;

    int ids[GU];
#pragma unroll
    for (int u = 0; u < GU; u++)
        ids[u] = (int)__ldg(&out[IDX_OFF + r0 + 4*u]);

    float v[GU];
#pragma unroll
    for (int u = 0; u < GU; u++)
        v[u] = __ldg(&P[(size_t)ids[u]*CFEAT + c]);

#pragma unroll
    for (int u = 0; u < GU; u++)
        out[(r0 + 4*u)*67 + 3 + c] = v[u];

    if (c < 3) {
        float xv[GU];
#pragma unroll
        for (int u = 0; u < GU; u++)
            xv[u] = __ldg(&Xb[(size_t)ids[u]*3 + c]);
#pragma unroll
        for (int u = 0; u < GU; u++) {
            long r = r0 + 4*u;
            out[r*67 + c]         = xv[u];
            out[GX_OFF + r*3 + c] = xv[u];
        }
    }
}

extern "C" void kernel_launch(void* const* d_in, const int* in_sizes, int n_in,
                              void* d_out, int out_size)
{
    const float *new_xyz = nullptr, *xyz = nullptr, *points = nullptr;
    for (int i = 0; i < n_in; i++) {
        if      (in_sizes[i] == BATCH*NPOINT*3)     new_xyz = (const float*)d_in[i];
        else if (in_sizes[i] == BATCH*NDATA*3)      xyz     = (const float*)d_in[i];
        else if (in_sizes[i] == BATCH*NDATA*CFEAT)  points  = (const float*)d_in[i];
    }
    float* out = (float*)d_out;

    k_transpose<<<(BATCH*NDATA + 255)/256, 256>>>(xyz);

    dim3 gs(NPOINT/QB, BATCH);
    k_search<<<gs, WPB*32>>>(new_xyz, out);

    k_gather<<<(BATCH*NPOINT*NSAMPLE)/(4*GU), 256>>>(xyz, points, out);
}